// round 10
// baseline (speedup 1.0000x reference)
#include <cuda_runtime.h>

#define BATCH 1024
#define MASK 0xFFFFFFFFu

typedef unsigned long long ull;

__device__ __forceinline__ float tanh_ap(float x) {
    float y;
    asm("tanh.approx.f32 %0, %1;" : "=f"(y) : "f"(x));
    return y;
}
__device__ __forceinline__ ull pk(float lo, float hi) {
    ull r;
    asm("mov.b64 %0, {%1, %2};" : "=l"(r) : "f"(lo), "f"(hi));
    return r;
}
__device__ __forceinline__ void upk(float& lo, float& hi, ull v) {
    asm("mov.b64 {%0, %1}, %2;" : "=f"(lo), "=f"(hi) : "l"(v));
}
__device__ __forceinline__ ull fma2(ull a, ull b, ull c) {
    ull d;
    asm("fma.rn.f32x2 %0, %1, %2, %3;" : "=l"(d) : "l"(a), "l"(b), "l"(c));
    return d;
}
__device__ __forceinline__ ull add2(ull a, ull b) {
    ull d;
    asm("add.rn.f32x2 %0, %1, %2;" : "=l"(d) : "l"(a), "l"(b));
    return d;
}
__device__ __forceinline__ void store_pred(int flag, float* p, float v) {
    asm volatile(
        "{\n\t.reg .pred %%pp;\n\t"
        "setp.ne.s32 %%pp, %0, 0;\n\t"
        "@%%pp st.global.f32 [%1], %2;\n\t}"
        :: "r"(flag), "l"(p), "f"(v));
}

// Warp = 2 chains x 16 lanes. slot = lane&15; entity = slot>>1 (0=feeder,
// 1..6=layers 0..5, 7=head); e = slot&1 selects h-elems {0,1} or {2,3}.
// Each lane computes all 4 gates for its 2 elems and keeps a full 4-elem h
// copy in registers, laid out (ownA, ownB, partnerA, partnerB). Input comes
// from entity-1's same-e lane via shfl_up(2); partner halves via shfl_xor(1).
// Weight COLUMNS are permuted per-lane at init so layouts line up for free.
struct St {
    ull wi_if[2][4], wi_go[2][4];   // [own-elem][m] packed (i,f)/(g,o), pre-scaled
    ull wh_if[2][4], wh_go[2][4];
    ull b_if[2], b_go[2];
    float hf0, hf1, hf2, hf3;       // layer lanes: full 2h copy; feeder: x copy
    float cA, cB;                   // plain c for own 2 elems
    float rw0, rw1, rw2, rw3, rb;
    int l, isfeed, headflag, b;
};

template<bool G>
__device__ __forceinline__ void tick(int k, St& s, float& rxa, float& rxb,
                                     const float* __restrict__ xb,
                                     float* __restrict__ out)
{
    // Input vector: previous entity's full h (same-e lane), 4 shfls / 2 chains.
    const float iv0 = __shfl_up_sync(MASK, s.hf0, 2);
    const float iv1 = __shfl_up_sync(MASK, s.hf1, 2);
    const float iv2 = __shfl_up_sync(MASK, s.hf2, 2);
    const float iv3 = __shfl_up_sync(MASK, s.hf3, 2);

    const ull di0 = pk(iv0, iv0), di1 = pk(iv1, iv1);
    const ull di2 = pk(iv2, iv2), di3 = pk(iv3, iv3);
    const ull dh0 = pk(s.hf0, s.hf0), dh1 = pk(s.hf1, s.hf1);
    const ull dh2 = pk(s.hf2, s.hf2), dh3 = pk(s.hf3, s.hf3);

    // 8 parallel 4-deep fma2 chains (iv chains carry bias; h chains from zero).
    ull aif0 = s.b_if[0], ago0 = s.b_go[0], aif1 = s.b_if[1], ago1 = s.b_go[1];
    ull pif0 = 0, pgo0 = 0, pif1 = 0, pgo1 = 0;

    aif0 = fma2(s.wi_if[0][0], di0, aif0); pif0 = fma2(s.wh_if[0][0], dh0, pif0);
    ago0 = fma2(s.wi_go[0][0], di0, ago0); pgo0 = fma2(s.wh_go[0][0], dh0, pgo0);
    aif1 = fma2(s.wi_if[1][0], di0, aif1); pif1 = fma2(s.wh_if[1][0], dh0, pif1);
    ago1 = fma2(s.wi_go[1][0], di0, ago1); pgo1 = fma2(s.wh_go[1][0], dh0, pgo1);

    aif0 = fma2(s.wi_if[0][1], di1, aif0); pif0 = fma2(s.wh_if[0][1], dh1, pif0);
    ago0 = fma2(s.wi_go[0][1], di1, ago0); pgo0 = fma2(s.wh_go[0][1], dh1, pgo0);
    aif1 = fma2(s.wi_if[1][1], di1, aif1); pif1 = fma2(s.wh_if[1][1], dh1, pif1);
    ago1 = fma2(s.wi_go[1][1], di1, ago1); pgo1 = fma2(s.wh_go[1][1], dh1, pgo1);

    aif0 = fma2(s.wi_if[0][2], di2, aif0); pif0 = fma2(s.wh_if[0][2], dh2, pif0);
    ago0 = fma2(s.wi_go[0][2], di2, ago0); pgo0 = fma2(s.wh_go[0][2], dh2, pgo0);
    aif1 = fma2(s.wi_if[1][2], di2, aif1); pif1 = fma2(s.wh_if[1][2], dh2, pif1);
    ago1 = fma2(s.wi_go[1][2], di2, ago1); pgo1 = fma2(s.wh_go[1][2], dh2, pgo1);

    aif0 = fma2(s.wi_if[0][3], di3, aif0); pif0 = fma2(s.wh_if[0][3], dh3, pif0);
    ago0 = fma2(s.wi_go[0][3], di3, ago0); pgo0 = fma2(s.wh_go[0][3], dh3, pgo0);
    aif1 = fma2(s.wi_if[1][3], di3, aif1); pif1 = fma2(s.wh_if[1][3], dh3, pif1);
    ago1 = fma2(s.wi_go[1][3], di3, ago1); pgo1 = fma2(s.wh_go[1][3], dh3, pgo1);

    const ull sif0 = add2(aif0, pif0);
    const ull sgo0 = add2(ago0, pgo0);
    const ull sif1 = add2(aif1, pif1);
    const ull sgo1 = add2(ago1, pgo1);

    float gi0, gf0, gg0, go0, gi1, gf1, gg1, go1;
    upk(gi0, gf0, sif0); upk(gg0, go0, sgo0);
    upk(gi1, gf1, sif1); upk(gg1, go1, sgo1);

    // Elem A epilogue (gates i,f,o folded by 0.5; c plain; h transported as 2h).
    const float tiA = tanh_ap(gi0);
    const float tfA = tanh_ap(gf0);
    const float ccA = tanh_ap(gg0);
    const float toA = tanh_ap(go0);
    const float uA  = fmaf(tfA, s.cA, s.cA);
    const float wA  = 0.5f * fmaf(tiA, ccA, ccA);
    const float ncA = fmaf(0.5f, uA, wA);
    const float thA = tanh_ap(ncA);
    const float nhA = fmaf(toA, thA, thA);

    // Elem B epilogue.
    const float tiB = tanh_ap(gi1);
    const float tfB = tanh_ap(gf1);
    const float ccB = tanh_ap(gg1);
    const float toB = tanh_ap(go1);
    const float uB  = fmaf(tfB, s.cB, s.cB);
    const float wB  = 0.5f * fmaf(tiB, ccB, ccB);
    const float ncB = fmaf(0.5f, uB, wB);
    const float thB = tanh_ap(ncB);
    const float nhB = fmaf(toB, thB, thB);

    // Head: slot 14 (e=0) sees layer-5 h in natural order via iv. rw pre-0.5.
    {
        float y = s.rb;
        y = fmaf(s.rw0, iv0, y);
        y = fmaf(s.rw1, iv1, y);
        y = fmaf(s.rw2, iv2, y);
        y = fmaf(s.rw3, iv3, y);
        const int kh = k - 6;
        const int hok = G ? ((unsigned)kh < 2048) : 1;
        const int tc = G ? (kh < 0 ? 0 : (kh > 2047 ? 2047 : kh)) : kh;
        store_pred(s.headflag & hok, out + (size_t)tc * BATCH + s.b, y);
    }

    // Consume prefetched x pair (this lane's 2 components), refill slot (+4).
    const float xA = rxa, xB = rxb;
    {
        int tp = k + 5;
        if (G) tp = tp > 2047 ? 2047 : tp;
        const float2 xf = *(const float2*)(xb + (size_t)tp * 4096);
        rxa = xf.x; rxb = xf.y;
    }

    // State update + partner exchange (2 shfls). Feeder injects x components.
    const int valid = G ? ((unsigned)(k - s.l) < 2048) : 1;
    float sel0 = valid ? nhA : s.hf0;
    float sel1 = valid ? nhB : s.hf1;
    sel0 = s.isfeed ? xA : sel0;
    sel1 = s.isfeed ? xB : sel1;
    const float p2 = __shfl_xor_sync(MASK, sel0, 1);
    const float p3 = __shfl_xor_sync(MASK, sel1, 1);
    s.hf0 = sel0; s.hf1 = sel1; s.hf2 = p2; s.hf3 = p3;
    s.cA = valid ? ncA : s.cA;
    s.cB = valid ? ncB : s.cB;
}

__global__ __launch_bounds__(32) void lstm_reg_kernel(
    const float* __restrict__ x,      // [S, B, 4]
    const float* __restrict__ w_ih,   // [6, 16, 4]
    const float* __restrict__ w_hh,   // [6, 16, 4]
    const float* __restrict__ b_ih,   // [6, 16]
    const float* __restrict__ b_hh,   // [6, 16]
    const float* __restrict__ reg_w,  // [1, 4]
    const float* __restrict__ reg_b,  // [1]
    float* __restrict__ out)          // [S, B, 1]
{
    const int lane = threadIdx.x & 31;
    const int c = lane >> 4;          // chain within warp
    const int slot = lane & 15;
    const int entity = slot >> 1;     // 0 feeder, 1..6 layers, 7 head
    const int e = slot & 1;           // elem half: 0 -> {0,1}, 1 -> {2,3}

    St s;
    s.b = blockIdx.x * 2 + c;
    s.l = entity - 1;
    s.isfeed = (entity == 0);
    s.headflag = (slot == 14);

    // Zero weights, then fill for layer lanes with per-lane column permutation
    // perm(m) = (m + 2e) & 3 so every lane's h layout is (own2, partner2).
#pragma unroll
    for (int oe = 0; oe < 2; ++oe) {
#pragma unroll
        for (int m = 0; m < 4; ++m) {
            s.wi_if[oe][m] = 0; s.wi_go[oe][m] = 0;
            s.wh_if[oe][m] = 0; s.wh_go[oe][m] = 0;
        }
        s.b_if[oe] = 0; s.b_go[oe] = 0;
    }
    if (entity >= 1 && entity <= 6) {
        const int l = entity - 1;
        const float isc = (l == 0) ? 1.0f : 0.5f;   // layer0 input is raw x
#pragma unroll
        for (int oe = 0; oe < 2; ++oe) {
            const int elem = 2 * e + oe;
            const int ri = l * 16 + 0 + elem;    // gate order i,f,g,o
            const int rf = l * 16 + 4 + elem;
            const int rg = l * 16 + 8 + elem;
            const int ro = l * 16 + 12 + elem;
#pragma unroll
            for (int m = 0; m < 4; ++m) {
                const int pc = (m + 2 * e) & 3;
                s.wi_if[oe][m] = pk(w_ih[ri * 4 + pc] * 0.5f * isc,
                                    w_ih[rf * 4 + pc] * 0.5f * isc);
                s.wi_go[oe][m] = pk(w_ih[rg * 4 + pc] * isc,
                                    w_ih[ro * 4 + pc] * 0.5f * isc);
                s.wh_if[oe][m] = pk(w_hh[ri * 4 + pc] * 0.25f,   // 0.5 gate * 0.5 (2h)
                                    w_hh[rf * 4 + pc] * 0.25f);
                s.wh_go[oe][m] = pk(w_hh[rg * 4 + pc] * 0.5f,
                                    w_hh[ro * 4 + pc] * 0.25f);
            }
            s.b_if[oe] = pk((b_ih[ri] + b_hh[ri]) * 0.5f,
                            (b_ih[rf] + b_hh[rf]) * 0.5f);
            s.b_go[oe] = pk((b_ih[rg] + b_hh[rg]) * 1.0f,
                            (b_ih[ro] + b_hh[ro]) * 0.5f);
        }
    }
    s.rw0 = reg_w[0] * 0.5f; s.rw1 = reg_w[1] * 0.5f;
    s.rw2 = reg_w[2] * 0.5f; s.rw3 = reg_w[3] * 0.5f;
    s.rb  = reg_b[0];

    // Init state. Feeder holds x[0] in its per-lane layout; layers start at 0.
    s.cA = 0.f; s.cB = 0.f;
    {
        const float4 x0v = *(const float4*)(x + (size_t)s.b * 4);
        const float q0 = e ? x0v.z : x0v.x;
        const float q1 = e ? x0v.w : x0v.y;
        const float q2 = e ? x0v.x : x0v.z;
        const float q3 = e ? x0v.y : x0v.w;
        s.hf0 = s.isfeed ? q0 : 0.f;
        s.hf1 = s.isfeed ? q1 : 0.f;
        s.hf2 = s.isfeed ? q2 : 0.f;
        s.hf3 = s.isfeed ? q3 : 0.f;
    }

    // Per-lane x base: this lane's 2 components (elems 2e, 2e+1) of batch s.b.
    const float* xb = x + (size_t)s.b * 4 + 2 * e;

    // Prefetch ring (4 deep): slot u holds x[k+1] components for tick k ≡ u.
    float rxa[4], rxb[4];
#pragma unroll
    for (int u = 0; u < 4; ++u) {
        const float2 xf = *(const float2*)(xb + (size_t)(u + 1) * 4096);
        rxa[u] = xf.x; rxb[u] = xf.y;
    }

    // ---- fill: ticks 0..7 (guarded) ----
#pragma unroll
    for (int u = 0; u < 8; ++u)
        tick<true>(u, s, rxa[u & 3], rxb[u & 3], xb, out);

    // ---- main: ticks 8..2039, guard-free ----
#pragma unroll 1
    for (int kc = 8; kc < 2040; kc += 4) {
#pragma unroll
        for (int u = 0; u < 4; ++u)
            tick<false>(kc + u, s, rxa[u], rxb[u], xb, out);
    }

    // ---- drain: ticks 2040..2053 (guarded) ----
#pragma unroll 1
    for (int kc = 2040; kc < 2056; kc += 4) {
#pragma unroll
        for (int u = 0; u < 4; ++u) {
            const int k = kc + u;
            if (k < 2054)
                tick<true>(k, s, rxa[u], rxb[u], xb, out);
        }
    }
}

extern "C" void kernel_launch(void* const* d_in, const int* in_sizes, int n_in,
                              void* d_out, int out_size) {
    const float* x     = (const float*)d_in[0];
    const float* w_ih  = (const float*)d_in[1];
    const float* w_hh  = (const float*)d_in[2];
    const float* b_ih  = (const float*)d_in[3];
    const float* b_hh  = (const float*)d_in[4];
    const float* reg_w = (const float*)d_in[5];
    const float* reg_b = (const float*)d_in[6];
    float* out = (float*)d_out;

    // 512 warps, each carrying 2 chains of 16 lanes.
    lstm_reg_kernel<<<512, 32>>>(x, w_ih, w_hh, b_ih, b_hh, reg_w, reg_b, out);
}